// round 15
// baseline (speedup 1.0000x reference)
#include <cuda_runtime.h>

#define D_DIM 64
#define H_DIM 256
#define W_DIM 256
#define PLANE (H_DIM * W_DIM)
#define D_CHUNK 8   // outputs per block along D (4 shared pairs)

// compare-exchange on the ALU pipe (FMNMX x2): a=min, b=max
__device__ __forceinline__ void s2(float& a, float& b) {
    float t = fminf(a, b);
    b = fmaxf(a, b);
    a = t;
}

// Hybrid compare-exchange: 1 alu op (FMNMX) + 2 fma-pipe ops (FADD).
// max = (a+b) - min(a,b), exact to <=1 ulp. Balances alu/fma pipe load.
__device__ __forceinline__ void s2h(float& a, float& b) {
    float s  = a + b;          // fma pipe
    float mn = fminf(a, b);    // alu pipe (independent of s)
    b = s - mn;                // fma pipe
    a = mn;
}

// Optimal 9-input sorting network: 25 comparators, depth 7.
// HYB: layers 4-7 (13 CEs) hybrid, layers 1-3 (12 CEs) pure alu —
// the LP-balanced alu/fma/issue split (x~24 pure-alu CEs per pair).
template <bool HYB>
__device__ __forceinline__ void sort9(float* v) {
    s2(v[0],v[3]); s2(v[1],v[7]); s2(v[2],v[5]); s2(v[4],v[8]);
    s2(v[0],v[7]); s2(v[2],v[4]); s2(v[3],v[8]); s2(v[5],v[6]);
    s2(v[0],v[2]); s2(v[1],v[3]); s2(v[4],v[5]); s2(v[7],v[8]);
    if (HYB) {
        s2h(v[1],v[4]); s2h(v[3],v[6]); s2h(v[5],v[7]);
        s2h(v[0],v[1]); s2h(v[2],v[4]); s2h(v[3],v[5]); s2h(v[6],v[8]);
        s2h(v[2],v[3]); s2h(v[4],v[5]); s2h(v[6],v[7]);
        s2h(v[1],v[2]); s2h(v[3],v[4]); s2h(v[5],v[6]);
    } else {
        s2(v[1],v[4]); s2(v[3],v[6]); s2(v[5],v[7]);
        s2(v[0],v[1]); s2(v[2],v[4]); s2(v[3],v[5]); s2(v[6],v[8]);
        s2(v[2],v[3]); s2(v[4],v[5]); s2(v[6],v[7]);
        s2(v[1],v[2]); s2(v[3],v[4]); s2(v[5],v[6]);
    }
}

// ---- Batcher odd-even merges, hybrid comparator (merge99 path) ----
__device__ __forceinline__ void merge11h(const float* a, const float* b, float* c) {
    c[0] = a[0]; c[1] = b[0]; s2h(c[0], c[1]);
}
__device__ __forceinline__ void merge22h(const float* a, const float* b, float* c) {
    float ae[1] = {a[0]}, be[1] = {b[0]}, ao[1] = {a[1]}, bo[1] = {b[1]};
    float e[2], o[2];
    merge11h(ae, be, e); merge11h(ao, bo, o);
    c[0] = e[0];
    c[1] = o[0]; c[2] = e[1]; s2h(c[1], c[2]);
    c[3] = o[1];
}
__device__ __forceinline__ void merge33h(const float* a, const float* b, float* c) {
    float ae[2] = {a[0], a[2]}, be[2] = {b[0], b[2]};
    float ao[1] = {a[1]},       bo[1] = {b[1]};
    float e[4], o[2];
    merge22h(ae, be, e); merge11h(ao, bo, o);
    c[0] = e[0];
    c[1] = o[0]; c[2] = e[1]; s2h(c[1], c[2]);
    c[3] = o[1]; c[4] = e[2]; s2h(c[3], c[4]);
    c[5] = e[3];
}
__device__ __forceinline__ void merge44h(const float* a, const float* b, float* c) {
    float ae[2] = {a[0], a[2]}, be[2] = {b[0], b[2]};
    float ao[2] = {a[1], a[3]}, bo[2] = {b[1], b[3]};
    float e[4], o[4];
    merge22h(ae, be, e); merge22h(ao, bo, o);
    c[0] = e[0];
    c[1] = o[0]; c[2] = e[1]; s2h(c[1], c[2]);
    c[3] = o[1]; c[4] = e[2]; s2h(c[3], c[4]);
    c[5] = o[2]; c[6] = e[3]; s2h(c[5], c[6]);
    c[7] = o[3];
}
__device__ __forceinline__ void merge55h(const float* a, const float* b, float* c) {
    float ae[3] = {a[0], a[2], a[4]}, be[3] = {b[0], b[2], b[4]};
    float ao[2] = {a[1], a[3]},       bo[2] = {b[1], b[3]};
    float e[6], o[4];
    merge33h(ae, be, e); merge22h(ao, bo, o);
    c[0] = e[0];
#pragma unroll
    for (int i = 1; i <= 4; ++i) { c[2*i-1] = o[i-1]; c[2*i] = e[i]; s2h(c[2*i-1], c[2*i]); }
    c[9] = e[5];
}
// Full merge of two sorted 9s into sorted 18, hybrid comparators; only
// c[4..13] are consumed, comparators feeding only the ends are dead-coded.
__device__ __forceinline__ void merge99h(const float* a, const float* b, float* c) {
    float ae[5] = {a[0], a[2], a[4], a[6], a[8]};
    float be[5] = {b[0], b[2], b[4], b[6], b[8]};
    float ao[4] = {a[1], a[3], a[5], a[7]};
    float bo[4] = {b[1], b[3], b[5], b[7]};
    float e[10], o[8];
    merge55h(ae, be, e); merge44h(ao, bo, o);
    c[0] = e[0];
#pragma unroll
    for (int i = 1; i <= 8; ++i) { c[2*i-1] = o[i-1]; c[2*i] = e[i]; s2h(c[2*i-1], c[2*i]); }
    c[17] = e[9];
}

// 10th smallest of sorted X[0..8] ∪ sorted T[0..9]  (== median of the 27-window).
// Closed form: max( T[0], max_i min(X[i], T[9-i]) ).  (alu pipe singles)
__device__ __forceinline__ float select10(const float* X, const float* T) {
    float c0 = T[0];
    float c1 = fminf(X[0], T[9]);
    float c2 = fminf(X[1], T[8]);
    float c3 = fminf(X[2], T[7]);
    float c4 = fminf(X[3], T[6]);
    float c5 = fminf(X[4], T[5]);
    float c6 = fminf(X[5], T[4]);
    float c7 = fminf(X[6], T[3]);
    float c8 = fminf(X[7], T[2]);
    float c9 = fminf(X[8], T[1]);
    float m01 = fmaxf(c0, c1), m23 = fmaxf(c2, c3);
    float m45 = fmaxf(c4, c5), m67 = fmaxf(c6, c7);
    float m89 = fmaxf(c8, c9);
    return fmaxf(fmaxf(fmaxf(m01, m23), fmaxf(m45, m67)), m89);
}

// Load the 3x3 (h,w) neighborhood of one D-plane with zero padding and a
// whole-plane validity predicate v (LDG offsets stay compile-time immediates).
__device__ __forceinline__ void load9v(const float* __restrict__ q, float* P,
                                       bool hm, bool hp, bool wm, bool wp, bool v) {
    P[0] = (v && hm && wm) ? __ldg(q - W_DIM - 1) : 0.0f;
    P[1] = (v && hm)       ? __ldg(q - W_DIM)     : 0.0f;
    P[2] = (v && hm && wp) ? __ldg(q - W_DIM + 1) : 0.0f;
    P[3] = (v && wm)       ? __ldg(q - 1)         : 0.0f;
    P[4] = (v)             ? __ldg(q)             : 0.0f;
    P[5] = (v && wp)       ? __ldg(q + 1)         : 0.0f;
    P[6] = (v && hp && wm) ? __ldg(q + W_DIM - 1) : 0.0f;
    P[7] = (v && hp)       ? __ldg(q + W_DIM)     : 0.0f;
    P[8] = (v && hp && wp) ? __ldg(q + W_DIM + 1) : 0.0f;
}

__global__ void __launch_bounds__(128, 10)
median3d_kernel(const float* __restrict__ x, float* __restrict__ y) {
    const int w = blockIdx.x * 128 + threadIdx.x;   // 0..255
    const int h = blockIdx.y;                       // 0..255
    const int d0 = blockIdx.z * D_CHUNK;

    const bool wm = (w > 0), wp = (w < W_DIM - 1);
    const bool hm = (h > 0), hp = (h < H_DIM - 1);

    const float* pb = x + (size_t)d0 * PLANE + (size_t)h * W_DIM + w;  // plane d0
    float* ob = y + (size_t)d0 * PLANE + (size_t)h * W_DIM + w;        // output base

    float Pm[9], P0[9], P1[9], P2[9];   // sorted planes d-1, d, d+1, d+2
    float c[18];

    // planes d0-1 (zero pad if d0==0) and d0 — batched loads.
    // When d0==0 every predicate of the first load9v is false: the LDGs are
    // predicated off and never issue addresses.
    load9v(pb - PLANE, Pm, hm, hp, wm, wp, d0 != 0);
    load9v(pb, P0, hm, hp, wm, wp, true);
    sort9<false>(Pm);
    sort9<false>(P0);

#pragma unroll
    for (int pp = 0; pp < D_CHUNK / 2; ++pp) {
        const int dd = 2 * pp;          // pair (d0+dd, d0+dd+1)

        // Batch BOTH planes' 18 predicated loads up front (branch-free).
        const bool v2 = (d0 + dd + 2 < D_DIM);
        const float* q2 = pb + (size_t)(v2 ? (dd + 2) : (dd + 1)) * PLANE;

        load9v(pb + (size_t)(dd + 1) * PLANE, P1, hm, hp, wm, wp, true);
        load9v(q2, P2, hm, hp, wm, wp, v2);

        sort9<true>(P1);
        sort9<true>(P2);                // zeros sort to zeros in pad case

        // shared sorted merge of the pair's planes (hybrid comparators);
        // middle 10 = c[4..13]
        merge99h(P0, P1, c);

        // two independent rank selections on the ALU pipe (high ILP)
        ob[(size_t)dd * PLANE]       = select10(Pm, c + 4);
        ob[(size_t)(dd + 1) * PLANE] = select10(P2, c + 4);

        // slide by 2: Pm <- P1, P0 <- P2 (register-renamed under full unroll)
#pragma unroll
        for (int i = 0; i < 9; ++i) { Pm[i] = P1[i]; P0[i] = P2[i]; }
    }
}

extern "C" void kernel_launch(void* const* d_in, const int* in_sizes, int n_in,
                              void* d_out, int out_size) {
    const float* x = (const float*)d_in[0];
    float* y = (float*)d_out;
    dim3 block(128, 1, 1);
    dim3 grid(W_DIM / 128, H_DIM, D_DIM / D_CHUNK);  // (2, 256, 8) = 4096 CTAs
    median3d_kernel<<<grid, block>>>(x, y);
}

// round 16
// speedup vs baseline: 1.0350x; 1.0350x over previous
#include <cuda_runtime.h>

#define D_DIM 64
#define H_DIM 256
#define W_DIM 256
#define PLANE (H_DIM * W_DIM)
#define D_CHUNK 8   // outputs per block along D (4 shared pairs)

// compare-exchange on the ALU pipe (FMNMX x2): a=min, b=max
__device__ __forceinline__ void s2(float& a, float& b) {
    float t = fminf(a, b);
    b = fmaxf(a, b);
    a = t;
}

// Hybrid compare-exchange: 1 alu op (FMNMX) + 2 fma-pipe ops (FADD).
// max = (a+b) - min(a,b), exact to <=1 ulp. Balances alu/fma pipe load.
__device__ __forceinline__ void s2h(float& a, float& b) {
    float s  = a + b;          // fma pipe
    float mn = fminf(a, b);    // alu pipe (independent of s)
    b = s - mn;                // fma pipe
    a = mn;
}

// Optimal 9-input sorting network: 25 comparators, depth 7.
// HYB: last two layers (6 CEs) hybrid — R14's empirically best pipe split.
template <bool HYB>
__device__ __forceinline__ void sort9(float* v) {
    s2(v[0],v[3]); s2(v[1],v[7]); s2(v[2],v[5]); s2(v[4],v[8]);
    s2(v[0],v[7]); s2(v[2],v[4]); s2(v[3],v[8]); s2(v[5],v[6]);
    s2(v[0],v[2]); s2(v[1],v[3]); s2(v[4],v[5]); s2(v[7],v[8]);
    s2(v[1],v[4]); s2(v[3],v[6]); s2(v[5],v[7]);
    s2(v[0],v[1]); s2(v[2],v[4]); s2(v[3],v[5]); s2(v[6],v[8]);
    if (HYB) {
        s2h(v[2],v[3]); s2h(v[4],v[5]); s2h(v[6],v[7]);
        s2h(v[1],v[2]); s2h(v[3],v[4]); s2h(v[5],v[6]);
    } else {
        s2(v[2],v[3]); s2(v[4],v[5]); s2(v[6],v[7]);
        s2(v[1],v[2]); s2(v[3],v[4]); s2(v[5],v[6]);
    }
}

// ---- Batcher odd-even merges, hybrid comparator (merge99 path) ----
__device__ __forceinline__ void merge11h(const float* a, const float* b, float* c) {
    c[0] = a[0]; c[1] = b[0]; s2h(c[0], c[1]);
}
__device__ __forceinline__ void merge22h(const float* a, const float* b, float* c) {
    float ae[1] = {a[0]}, be[1] = {b[0]}, ao[1] = {a[1]}, bo[1] = {b[1]};
    float e[2], o[2];
    merge11h(ae, be, e); merge11h(ao, bo, o);
    c[0] = e[0];
    c[1] = o[0]; c[2] = e[1]; s2h(c[1], c[2]);
    c[3] = o[1];
}
__device__ __forceinline__ void merge33h(const float* a, const float* b, float* c) {
    float ae[2] = {a[0], a[2]}, be[2] = {b[0], b[2]};
    float ao[1] = {a[1]},       bo[1] = {b[1]};
    float e[4], o[2];
    merge22h(ae, be, e); merge11h(ao, bo, o);
    c[0] = e[0];
    c[1] = o[0]; c[2] = e[1]; s2h(c[1], c[2]);
    c[3] = o[1]; c[4] = e[2]; s2h(c[3], c[4]);
    c[5] = e[3];
}
__device__ __forceinline__ void merge44h(const float* a, const float* b, float* c) {
    float ae[2] = {a[0], a[2]}, be[2] = {b[0], b[2]};
    float ao[2] = {a[1], a[3]}, bo[2] = {b[1], b[3]};
    float e[4], o[4];
    merge22h(ae, be, e); merge22h(ao, bo, o);
    c[0] = e[0];
    c[1] = o[0]; c[2] = e[1]; s2h(c[1], c[2]);
    c[3] = o[1]; c[4] = e[2]; s2h(c[3], c[4]);
    c[5] = o[2]; c[6] = e[3]; s2h(c[5], c[6]);
    c[7] = o[3];
}
__device__ __forceinline__ void merge55h(const float* a, const float* b, float* c) {
    float ae[3] = {a[0], a[2], a[4]}, be[3] = {b[0], b[2], b[4]};
    float ao[2] = {a[1], a[3]},       bo[2] = {b[1], b[3]};
    float e[6], o[4];
    merge33h(ae, be, e); merge22h(ao, bo, o);
    c[0] = e[0];
#pragma unroll
    for (int i = 1; i <= 4; ++i) { c[2*i-1] = o[i-1]; c[2*i] = e[i]; s2h(c[2*i-1], c[2*i]); }
    c[9] = e[5];
}
// Full merge of two sorted 9s into sorted 18, hybrid comparators; only
// c[4..13] are consumed, comparators feeding only the ends are dead-coded.
__device__ __forceinline__ void merge99h(const float* a, const float* b, float* c) {
    float ae[5] = {a[0], a[2], a[4], a[6], a[8]};
    float be[5] = {b[0], b[2], b[4], b[6], b[8]};
    float ao[4] = {a[1], a[3], a[5], a[7]};
    float bo[4] = {b[1], b[3], b[5], b[7]};
    float e[10], o[8];
    merge55h(ae, be, e); merge44h(ao, bo, o);
    c[0] = e[0];
#pragma unroll
    for (int i = 1; i <= 8; ++i) { c[2*i-1] = o[i-1]; c[2*i] = e[i]; s2h(c[2*i-1], c[2*i]); }
    c[17] = e[9];
}

// 10th smallest of sorted X[0..8] ∪ sorted T[0..9]  (== median of the 27-window).
// Closed form: max( T[0], max_i min(X[i], T[9-i]) ).  (alu pipe singles)
__device__ __forceinline__ float select10(const float* X, const float* T) {
    float c0 = T[0];
    float c1 = fminf(X[0], T[9]);
    float c2 = fminf(X[1], T[8]);
    float c3 = fminf(X[2], T[7]);
    float c4 = fminf(X[3], T[6]);
    float c5 = fminf(X[4], T[5]);
    float c6 = fminf(X[5], T[4]);
    float c7 = fminf(X[6], T[3]);
    float c8 = fminf(X[7], T[2]);
    float c9 = fminf(X[8], T[1]);
    float m01 = fmaxf(c0, c1), m23 = fmaxf(c2, c3);
    float m45 = fmaxf(c4, c5), m67 = fmaxf(c6, c7);
    float m89 = fmaxf(c8, c9);
    return fmaxf(fmaxf(fmaxf(m01, m23), fmaxf(m45, m67)), m89);
}

// Load the 3x3 (h,w) neighborhood of one D-plane with zero padding and a
// whole-plane validity predicate v (LDG offsets stay compile-time immediates).
// When v is a compile-time constant true, the v&& terms fold away entirely.
__device__ __forceinline__ void load9v(const float* __restrict__ q, float* P,
                                       bool hm, bool hp, bool wm, bool wp, bool v) {
    P[0] = (v && hm && wm) ? __ldg(q - W_DIM - 1) : 0.0f;
    P[1] = (v && hm)       ? __ldg(q - W_DIM)     : 0.0f;
    P[2] = (v && hm && wp) ? __ldg(q - W_DIM + 1) : 0.0f;
    P[3] = (v && wm)       ? __ldg(q - 1)         : 0.0f;
    P[4] = (v)             ? __ldg(q)             : 0.0f;
    P[5] = (v && wp)       ? __ldg(q + 1)         : 0.0f;
    P[6] = (v && hp && wm) ? __ldg(q + W_DIM - 1) : 0.0f;
    P[7] = (v && hp)       ? __ldg(q + W_DIM)     : 0.0f;
    P[8] = (v && hp && wp) ? __ldg(q + W_DIM + 1) : 0.0f;
}

__global__ void __launch_bounds__(128, 10)
median3d_kernel(const float* __restrict__ x, float* __restrict__ y) {
    const int w = blockIdx.x * 128 + threadIdx.x;   // 0..255
    const int h = blockIdx.y;                       // 0..255
    const int d0 = blockIdx.z * D_CHUNK;

    const bool wm = (w > 0), wp = (w < W_DIM - 1);
    const bool hm = (h > 0), hp = (h < H_DIM - 1);

    const float* pb = x + (size_t)d0 * PLANE + (size_t)h * W_DIM + w;  // plane d0
    float* ob = y + (size_t)d0 * PLANE + (size_t)h * W_DIM + w;        // output base

    float Pm[9], P0[9], P1[9], P2[9];   // sorted planes d-1, d, d+1, d+2
    float c[18];

    // planes d0-1 (zero pad if d0==0) and d0 — batched loads.
    // When d0==0 every predicate of the first load9v is false: the LDGs are
    // predicated off and never issue addresses.
    load9v(pb - PLANE, Pm, hm, hp, wm, wp, d0 != 0);
    load9v(pb, P0, hm, hp, wm, wp, true);
    sort9<false>(Pm);
    sort9<false>(P0);

#pragma unroll
    for (int pp = 0; pp < D_CHUNK / 2; ++pp) {
        const int dd = 2 * pp;          // pair (d0+dd, d0+dd+1)

        // Plane d0+dd+2 validity. For pp < 3 this is PROVABLE at compile time
        // (d0 <= 56, dd <= 4 -> d0+dd+2 <= 62 < 64), so under full unroll the
        // ternary below folds to `true` and all v2 predicate logic vanishes
        // from the first three iterations. Only the last iteration carries the
        // runtime check (false only for blockIdx.z == 7).
        const bool v2 = (pp < D_CHUNK / 2 - 1) || (d0 + D_CHUNK < D_DIM);
        // Clamped pointer keeps the address legal even when predicated off.
        const float* q2 = pb + (size_t)(v2 ? (dd + 2) : (dd + 1)) * PLANE;

        // Batch BOTH planes' 18 predicated loads up front (branch-free).
        load9v(pb + (size_t)(dd + 1) * PLANE, P1, hm, hp, wm, wp, true);
        load9v(q2, P2, hm, hp, wm, wp, v2);

        sort9<true>(P1);
        sort9<true>(P2);                // zeros sort to zeros in pad case

        // shared sorted merge of the pair's planes (hybrid comparators);
        // middle 10 = c[4..13]
        merge99h(P0, P1, c);

        // two independent rank selections on the ALU pipe (high ILP)
        ob[(size_t)dd * PLANE]       = select10(Pm, c + 4);
        ob[(size_t)(dd + 1) * PLANE] = select10(P2, c + 4);

        // slide by 2: Pm <- P1, P0 <- P2 (register-renamed under full unroll)
#pragma unroll
        for (int i = 0; i < 9; ++i) { Pm[i] = P1[i]; P0[i] = P2[i]; }
    }
}

extern "C" void kernel_launch(void* const* d_in, const int* in_sizes, int n_in,
                              void* d_out, int out_size) {
    const float* x = (const float*)d_in[0];
    float* y = (float*)d_out;
    dim3 block(128, 1, 1);
    dim3 grid(W_DIM / 128, H_DIM, D_DIM / D_CHUNK);  // (2, 256, 8) = 4096 CTAs
    median3d_kernel<<<grid, block>>>(x, y);
}